// round 8
// baseline (speedup 1.0000x reference)
#include <cuda_runtime.h>
#include <cuda_fp16.h>
#include <cstdint>
#include <cstddef>

#define DINL __device__ __forceinline__

namespace {

constexpr int NB = 32;
constexpr int CH = 64;
constexpr int T  = 2048;
constexpr int SE = 77;
constexpr int L  = SE + T;                 // 2125
constexpr int BT = 64;                     // query tile (2 warps x m32)
constexpr int BS = 64;                     // key tile
constexpr int NTILES = (L + BS - 1) / BS;  // 34
constexpr int LP = NTILES * BS;            // 2176
constexpr int NTH = 64;

constexpr float LOG2E = 1.4426950408889634f;

// SW128-swizzled smem: 128B rows, chunk (row,koff): addr = row*128 + (koff ^ ((row&7)<<4))
constexpr int OFF_Q = 0;                   // [64][128B] = 8192
constexpr int OFF_K = 8192;                // 2 bufs x [64][128B]
constexpr int OFF_V = 24576;               // 2 bufs
constexpr int KVBUF = 8192;
constexpr int SMEM_TOTAL = 40960;

// K scratch: [b][s][c] (GEMM1 B layout), V scratch: [b][c][s] (GEMM2 B layout)
__device__ __align__(16) __half g_K[(size_t)NB * LP * CH];
__device__ __align__(16) __half g_V[(size_t)NB * CH * LP];
__device__ int g_mask_flag;

DINL uint32_t smem_u32(const void* p) {
    uint32_t a;
    asm("{ .reg .u64 t; cvta.to.shared.u64 t, %1; cvt.u32.u64 %0, t; }" : "=r"(a) : "l"(p));
    return a;
}
DINL void ldsm4(uint32_t r[4], uint32_t addr) {
    asm volatile("ldmatrix.sync.aligned.m8n8.x4.shared.b16 {%0,%1,%2,%3}, [%4];"
                 : "=r"(r[0]), "=r"(r[1]), "=r"(r[2]), "=r"(r[3]) : "r"(addr));
}
DINL void mma_f16(float c[4], const uint32_t a[4], uint32_t b0, uint32_t b1) {
    asm volatile(
        "mma.sync.aligned.m16n8k16.row.col.f32.f16.f16.f32 "
        "{%0,%1,%2,%3}, {%4,%5,%6,%7}, {%8,%9}, {%0,%1,%2,%3};"
        : "+f"(c[0]), "+f"(c[1]), "+f"(c[2]), "+f"(c[3])
        : "r"(a[0]), "r"(a[1]), "r"(a[2]), "r"(a[3]), "r"(b0), "r"(b1));
}
DINL float ex2(float x) {
    float r;
    asm("ex2.approx.ftz.f32 %0, %1;" : "=f"(r) : "f"(x));
    return r;
}
DINL uint32_t f2h2(float a, float b) {       // pack {a -> lo, b -> hi}
    __half2 h = __floats2half2_rn(a, b);
    return *reinterpret_cast<uint32_t*>(&h);
}
DINL void cpa16(uint32_t dst, const void* src) {
    asm volatile("cp.async.cg.shared.global [%0], [%1], 16;" :: "r"(dst), "l"(src));
}
DINL void cpa_commit() { asm volatile("cp.async.commit_group;"); }
DINL void cpa_wait_all() { asm volatile("cp.async.wait_all;"); }

__global__ void reset_flag_kernel() { g_mask_flag = 0; }

__global__ void scan_mask_kernel(const float* __restrict__ m, int n) {
    bool nz = false;
    for (int i = blockIdx.x * blockDim.x + threadIdx.x; i < n; i += gridDim.x * blockDim.x)
        nz |= (m[i] != 0.0f);
    if (__syncthreads_or(nz) && threadIdx.x == 0) atomicOr(&g_mask_flag, 1);
}

// ---- pre-pass: fp32 K/V -> fp16 scratch (K transposed to [s][c]) ----
__global__ __launch_bounds__(256) void prepass_kernel(
    const float* __restrict__ qkv, const float* __restrict__ ekv)
{
    __shared__ float kb[64][65], vb[64][65];
    const int b  = blockIdx.y;
    const int s0 = blockIdx.x * 64;
    const float* qb = qkv + (size_t)b * (3 * CH * T);
    const float* eb = ekv + (size_t)b * (2 * CH * SE);

    for (int i = threadIdx.x; i < 4096; i += 256) {
        const int s = i & 63, c = i >> 6;
        const int sg = s0 + s;
        float kv = 0.f, vv = 0.f;
        if (sg < SE) {
            kv = eb[(size_t)c * SE + sg];
            vv = eb[(size_t)(CH + c) * SE + sg];
        } else if (sg < L) {
            kv = qb[(size_t)(CH + c) * T + (sg - SE)];
            vv = qb[(size_t)(2 * CH + c) * T + (sg - SE)];
        }
        kb[c][s] = kv;
        vb[c][s] = vv;
    }
    __syncthreads();

    __half2* K2 = (__half2*)(g_K + ((size_t)b * LP + s0) * CH);
    for (int i = threadIdx.x; i < 2048; i += 256) {   // K: [s][c], half2 on c
        const int c2 = i & 31, s = i >> 5;
        K2[s * 32 + c2] = __floats2half2_rn(kb[2 * c2][s], kb[2 * c2 + 1][s]);
    }
    __half2* V2 = (__half2*)(g_V + (size_t)b * CH * LP + s0);
    for (int i = threadIdx.x; i < 2048; i += 256) {   // V: [c][s], half2 on s
        const int s2 = i & 31, c = i >> 5;
        V2[c * (LP / 2) + s2] = __floats2half2_rn(vb[c][2 * s2], vb[c][2 * s2 + 1]);
    }
}

__global__ __launch_bounds__(NTH, 5) void attn_kernel(
    const float* __restrict__ qkv,
    const float* __restrict__ mask,
    float* __restrict__ out)
{
    extern __shared__ char smc[];
    const uint32_t sb = smem_u32(smc);

    const int tid  = threadIdx.x;
    const int warp = tid >> 5;               // 0..1
    const int lane = tid & 31;
    const int b  = blockIdx.y;
    const int t0 = blockIdx.x * BT;
    const float* qb = qkv + (size_t)b * (3 * CH * T);
    const int mflag = g_mask_flag;

    const __half* srcK = g_K + (size_t)b * LP * CH;
    const __half* srcV = g_V + (size_t)b * CH * LP;

    // ---- prefetch K/V tile 0 into buf 0 (64 thr -> 8 chunks each per buf) ----
    {
        #pragma unroll
        for (int it = 0; it < 8; it++) {
            const int idx = tid + it * 64;
            const int row = idx >> 3, q = idx & 7;
            const uint32_t sw = (uint32_t)(q * 16) ^ ((uint32_t)(row & 7) << 4);
            cpa16(sb + OFF_K + row * 128 + sw, srcK + (size_t)row * CH + q * 8);
            cpa16(sb + OFF_V + row * 128 + sw, srcV + (size_t)row * LP + q * 8);
        }
        cpa_commit();
    }

    // ---- Q tile: load, scale (0.125 * log2e folded), fp16, swizzled [t][c] ----
    for (int i = tid; i < BT * CH; i += NTH) {
        const int t = i & 63, c = i >> 6;
        const float v = qb[(size_t)c * T + t0 + t] * (0.125f * LOG2E);
        const uint32_t off = (uint32_t)(t * 128 + c * 2) ^ ((uint32_t)(t & 7) << 4);
        *(__half*)(smc + OFF_Q + off) = __float2half(v);
    }

    // ---- ldmatrix lane address geometry (SW128) ----
    const int mi = lane >> 3, ri = lane & 7;
    const uint32_t a_row  = (mi & 1) * 8 + ri;        // A m16k16
    const uint32_t a_koff = (mi >> 1) * 16;
    const uint32_t b_row  = (mi >> 1) * 8 + ri;       // B n16k16
    const uint32_t b_koff = (mi & 1) * 16;
    const uint32_t a_sw = (a_row & 7) << 4;
    const uint32_t b_sw = (b_row & 7) << 4;

    // warp covers rows [warp*32, warp*32+32): two m16 A tiles
    const uint32_t q_base0 = sb + OFF_Q + (warp * 32 + a_row) * 128;
    const uint32_t q_base1 = q_base0 + 16 * 128;
    const uint32_t kB = sb + OFF_K + b_row * 128;
    const uint32_t vB = sb + OFF_V + b_row * 128;

    const int trow0 = t0 + warp * 32 + (lane >> 2);   // +8, +16, +24 siblings

    float oaccA[8][4] = {}, oaccB[8][4] = {};
    float ls0 = 0.f, ls1 = 0.f, ls2 = 0.f, ls3 = 0.f;

    for (int tile = 0; tile < NTILES; tile++) {
        const int s0 = tile * BS;
        const uint32_t buf = (uint32_t)(tile & 1) * KVBUF;

        cpa_wait_all();
        __syncthreads();

        // ---- prefetch tile+1 into other buffer (overlaps with GEMMs) ----
        if (tile + 1 < NTILES) {
            const uint32_t nbuf = (uint32_t)((tile + 1) & 1) * KVBUF;
            const int ns0 = s0 + BS;
            #pragma unroll
            for (int it = 0; it < 8; it++) {
                const int idx = tid + it * 64;
                const int row = idx >> 3, q = idx & 7;
                const uint32_t sw = (uint32_t)(q * 16) ^ ((uint32_t)(row & 7) << 4);
                cpa16(sb + OFF_K + nbuf + row * 128 + sw,
                      srcK + (size_t)(ns0 + row) * CH + q * 8);
                cpa16(sb + OFF_V + nbuf + row * 128 + sw,
                      srcV + (size_t)row * LP + ns0 + q * 8);
            }
            cpa_commit();
        }

        // ---- GEMM1: S = Q*K, two m16 halves share each K fragment ----
        float saccA[8][4] = {}, saccB[8][4] = {};
        #pragma unroll
        for (int kk = 0; kk < 4; kk++) {
            uint32_t a0[4], a1[4];
            ldsm4(a0, q_base0 + ((a_koff + kk * 32) ^ a_sw));
            ldsm4(a1, q_base1 + ((a_koff + kk * 32) ^ a_sw));
            #pragma unroll
            for (int nb = 0; nb < 4; nb++) {
                uint32_t bk[4];
                ldsm4(bk, kB + buf + nb * 2048 + ((b_koff + kk * 32) ^ b_sw));
                mma_f16(saccA[2 * nb],     a0, bk[0], bk[1]);
                mma_f16(saccA[2 * nb + 1], a0, bk[2], bk[3]);
                mma_f16(saccB[2 * nb],     a1, bk[0], bk[1]);
                mma_f16(saccB[2 * nb + 1], a1, bk[2], bk[3]);
            }
        }

        // ---- softmax: hot path = bare ex2 + add ----
        if (!mflag && tile < NTILES - 1) {
            #pragma unroll
            for (int j = 0; j < 8; j++) {
                #pragma unroll
                for (int e = 0; e < 4; e++) {
                    const float pA = ex2(saccA[j][e]);
                    const float pB = ex2(saccB[j][e]);
                    saccA[j][e] = pA;
                    saccB[j][e] = pB;
                    if (e < 2) { ls0 += pA; ls2 += pB; }
                    else       { ls1 += pA; ls3 += pB; }
                }
            }
        } else {
            #pragma unroll
            for (int j = 0; j < 8; j++) {
                const int sgb = s0 + j * 8 + 2 * (lane & 3);
                #pragma unroll
                for (int e = 0; e < 4; e++) {
                    const int sg = sgb + (e & 1);
                    float scA = saccA[j][e], scB = saccB[j][e];
                    if (mflag && sg < L) {
                        const int ra = trow0 + ((e < 2) ? 0 : 8);
                        scA += mask[(size_t)ra * L + sg] * LOG2E;
                        scB += mask[(size_t)(ra + 16) * L + sg] * LOG2E;
                    }
                    float pA = ex2(scA), pB = ex2(scB);
                    pA = (sg < L) ? pA : 0.f;
                    pB = (sg < L) ? pB : 0.f;
                    saccA[j][e] = pA;
                    saccB[j][e] = pB;
                    if (e < 2) { ls0 += pA; ls2 += pB; }
                    else       { ls1 += pA; ls3 += pB; }
                }
            }
        }

        // ---- GEMM2: O += P*V, two m16 halves share each V fragment ----
        #pragma unroll
        for (int kk = 0; kk < 4; kk++) {
            const float* pA0 = saccA[2 * kk];
            const float* pA1 = saccA[2 * kk + 1];
            const float* pB0 = saccB[2 * kk];
            const float* pB1 = saccB[2 * kk + 1];
            uint32_t aA[4], aB[4];
            aA[0] = f2h2(pA0[0], pA0[1]);
            aA[1] = f2h2(pA0[2], pA0[3]);
            aA[2] = f2h2(pA1[0], pA1[1]);
            aA[3] = f2h2(pA1[2], pA1[3]);
            aB[0] = f2h2(pB0[0], pB0[1]);
            aB[1] = f2h2(pB0[2], pB0[3]);
            aB[2] = f2h2(pB1[0], pB1[1]);
            aB[3] = f2h2(pB1[2], pB1[3]);
            #pragma unroll
            for (int nb = 0; nb < 4; nb++) {
                uint32_t bv[4];
                ldsm4(bv, vB + buf + nb * 2048 + ((b_koff + kk * 32) ^ b_sw));
                mma_f16(oaccA[2 * nb],     aA, bv[0], bv[1]);
                mma_f16(oaccA[2 * nb + 1], aA, bv[2], bv[3]);
                mma_f16(oaccB[2 * nb],     aB, bv[0], bv[1]);
                mma_f16(oaccB[2 * nb + 1], aB, bv[2], bv[3]);
            }
        }
    }

    // ---- epilogue: reduce row sums, normalize, stage transpose, store ----
    ls0 += __shfl_xor_sync(0xffffffffu, ls0, 1);
    ls0 += __shfl_xor_sync(0xffffffffu, ls0, 2);
    ls1 += __shfl_xor_sync(0xffffffffu, ls1, 1);
    ls1 += __shfl_xor_sync(0xffffffffu, ls1, 2);
    ls2 += __shfl_xor_sync(0xffffffffu, ls2, 1);
    ls2 += __shfl_xor_sync(0xffffffffu, ls2, 2);
    ls3 += __shfl_xor_sync(0xffffffffu, ls3, 1);
    ls3 += __shfl_xor_sync(0xffffffffu, ls3, 2);
    const float rl0 = 1.0f / ls0, rl1 = 1.0f / ls1;
    const float rl2 = 1.0f / ls2, rl3 = 1.0f / ls3;

    __syncthreads();                           // done with Q/K smem
    float* os = (float*)smc;                   // reuse: [CH][68]
    const int tl0 = warp * 32 + (lane >> 2);
    #pragma unroll
    for (int jb = 0; jb < 8; jb++) {
        const int c0 = jb * 8 + 2 * (lane & 3);
        os[c0 * 68 + tl0]             = oaccA[jb][0] * rl0;
        os[(c0 + 1) * 68 + tl0]       = oaccA[jb][1] * rl0;
        os[c0 * 68 + tl0 + 8]         = oaccA[jb][2] * rl1;
        os[(c0 + 1) * 68 + tl0 + 8]   = oaccA[jb][3] * rl1;
        os[c0 * 68 + tl0 + 16]        = oaccB[jb][0] * rl2;
        os[(c0 + 1) * 68 + tl0 + 16]  = oaccB[jb][1] * rl2;
        os[c0 * 68 + tl0 + 24]        = oaccB[jb][2] * rl3;
        os[(c0 + 1) * 68 + tl0 + 24]  = oaccB[jb][3] * rl3;
    }
    __syncthreads();

    float* ob = out + (size_t)b * CH * T + t0;
    for (int i = tid; i < CH * BT; i += NTH) {
        const int c = i >> 6, t = i & 63;
        ob[(size_t)c * T + t] = os[c * 68 + t];
    }
}

} // anonymous namespace

extern "C" void kernel_launch(void* const* d_in, const int* in_sizes, int n_in,
                              void* d_out, int out_size)
{
    const float* qkv  = (const float*)d_in[0];
    const float* ekv  = (const float*)d_in[1];
    const float* mask = (const float*)d_in[2];
    float* out = (float*)d_out;
    (void)n_in; (void)out_size;

    cudaFuncSetAttribute(attn_kernel,
                         cudaFuncAttributeMaxDynamicSharedMemorySize, SMEM_TOTAL);

    reset_flag_kernel<<<1, 1>>>();
    scan_mask_kernel<<<1024, 256>>>(mask, in_sizes[2]);
    prepass_kernel<<<dim3(LP / 64, NB), 256>>>(qkv, ekv);

    dim3 grid(T / BT, NB);   // 32 x 32 = 1024 CTAs
    attn_kernel<<<grid, NTH, SMEM_TOTAL>>>(qkv, mask, out);
}

// round 9
// speedup vs baseline: 1.3386x; 1.3386x over previous
#include <cuda_runtime.h>
#include <cuda_fp16.h>
#include <cstdint>
#include <cstddef>

#define DINL __device__ __forceinline__

namespace {

constexpr int NB = 32;
constexpr int CH = 64;
constexpr int T  = 2048;
constexpr int SE = 77;
constexpr int L  = SE + T;                 // 2125
constexpr int BT = 128;                    // query tile (4 warps x m32)
constexpr int BS = 64;                     // key tile
constexpr int NTILES = (L + BS - 1) / BS;  // 34
constexpr int LP = NTILES * BS;            // 2176
constexpr int NTH = 128;

constexpr float LOG2E = 1.4426950408889634f;

// SW128-swizzled smem: 128B rows; addr = base + row*128 + (koff ^ ((row&7)<<4))
constexpr int OFF_Q = 0;                   // [128][128B] = 16384
constexpr int OFF_K = 16384;               // 2 bufs x [64][128B] = 2 x 8192
constexpr int OFF_V = 32768;               // 2 bufs
constexpr int KVBUF = 8192;
constexpr int SMEM_TOTAL = 49152;          // 4 CTAs/SM -> 192KB/SM

// K scratch: [b][s][c] (GEMM1 B layout), V scratch: [b][c][s] (GEMM2 B layout)
__device__ __align__(16) __half g_K[(size_t)NB * LP * CH];
__device__ __align__(16) __half g_V[(size_t)NB * CH * LP];
__device__ int g_mask_flag;

DINL uint32_t smem_u32(const void* p) {
    uint32_t a;
    asm("{ .reg .u64 t; cvta.to.shared.u64 t, %1; cvt.u32.u64 %0, t; }" : "=r"(a) : "l"(p));
    return a;
}
DINL void ldsm4(uint32_t r[4], uint32_t addr) {
    asm volatile("ldmatrix.sync.aligned.m8n8.x4.shared.b16 {%0,%1,%2,%3}, [%4];"
                 : "=r"(r[0]), "=r"(r[1]), "=r"(r[2]), "=r"(r[3]) : "r"(addr));
}
DINL void mma_f16(float c[4], const uint32_t a[4], uint32_t b0, uint32_t b1) {
    asm volatile(
        "mma.sync.aligned.m16n8k16.row.col.f32.f16.f16.f32 "
        "{%0,%1,%2,%3}, {%4,%5,%6,%7}, {%8,%9}, {%0,%1,%2,%3};"
        : "+f"(c[0]), "+f"(c[1]), "+f"(c[2]), "+f"(c[3])
        : "r"(a[0]), "r"(a[1]), "r"(a[2]), "r"(a[3]), "r"(b0), "r"(b1));
}
DINL float ex2(float x) {
    float r;
    asm("ex2.approx.ftz.f32 %0, %1;" : "=f"(r) : "f"(x));
    return r;
}
DINL uint32_t f2h2(float a, float b) {       // pack {a -> lo, b -> hi}
    __half2 h = __floats2half2_rn(a, b);
    return *reinterpret_cast<uint32_t*>(&h);
}
DINL void cpa16(uint32_t dst, const void* src) {
    asm volatile("cp.async.cg.shared.global [%0], [%1], 16;" :: "r"(dst), "l"(src));
}
DINL void cpa_commit() { asm volatile("cp.async.commit_group;"); }
DINL void cpa_wait_all() { asm volatile("cp.async.wait_all;"); }

__global__ void reset_flag_kernel() { g_mask_flag = 0; }

__global__ void scan_mask_kernel(const float* __restrict__ m, int n) {
    bool nz = false;
    for (int i = blockIdx.x * blockDim.x + threadIdx.x; i < n; i += gridDim.x * blockDim.x)
        nz |= (m[i] != 0.0f);
    if (__syncthreads_or(nz) && threadIdx.x == 0) atomicOr(&g_mask_flag, 1);
}

// ---- pre-pass: fp32 K/V -> fp16 scratch (K transposed to [s][c]) ----
__global__ __launch_bounds__(256) void prepass_kernel(
    const float* __restrict__ qkv, const float* __restrict__ ekv)
{
    __shared__ float kb[64][65], vb[64][65];
    const int b  = blockIdx.y;
    const int s0 = blockIdx.x * 64;
    const float* qb = qkv + (size_t)b * (3 * CH * T);
    const float* eb = ekv + (size_t)b * (2 * CH * SE);

    for (int i = threadIdx.x; i < 4096; i += 256) {
        const int s = i & 63, c = i >> 6;
        const int sg = s0 + s;
        float kv = 0.f, vv = 0.f;
        if (sg < SE) {
            kv = eb[(size_t)c * SE + sg];
            vv = eb[(size_t)(CH + c) * SE + sg];
        } else if (sg < L) {
            kv = qb[(size_t)(CH + c) * T + (sg - SE)];
            vv = qb[(size_t)(2 * CH + c) * T + (sg - SE)];
        }
        kb[c][s] = kv;
        vb[c][s] = vv;
    }
    __syncthreads();

    __half2* K2 = (__half2*)(g_K + ((size_t)b * LP + s0) * CH);
    for (int i = threadIdx.x; i < 2048; i += 256) {   // K: [s][c], half2 on c
        const int c2 = i & 31, s = i >> 5;
        K2[s * 32 + c2] = __floats2half2_rn(kb[2 * c2][s], kb[2 * c2 + 1][s]);
    }
    __half2* V2 = (__half2*)(g_V + (size_t)b * CH * LP + s0);
    for (int i = threadIdx.x; i < 2048; i += 256) {   // V: [c][s], half2 on s
        const int s2 = i & 31, c = i >> 5;
        V2[c * (LP / 2) + s2] = __floats2half2_rn(vb[c][2 * s2], vb[c][2 * s2 + 1]);
    }
}

__global__ __launch_bounds__(NTH, 4) void attn_kernel(
    const float* __restrict__ qkv,
    const float* __restrict__ mask,
    float* __restrict__ out)
{
    extern __shared__ char smc[];
    const uint32_t sb = smem_u32(smc);

    const int tid  = threadIdx.x;
    const int warp = tid >> 5;
    const int lane = tid & 31;
    const int b  = blockIdx.y;
    const int t0 = blockIdx.x * BT;
    const float* qb = qkv + (size_t)b * (3 * CH * T);
    const int mflag = g_mask_flag;

    const __half* srcK = g_K + (size_t)b * LP * CH;
    const __half* srcV = g_V + (size_t)b * CH * LP;

    // ---- prefetch K/V tile 0 into buf 0 (128 thr, 512 chunks each of K,V) ----
    {
        #pragma unroll
        for (int it = 0; it < 4; it++) {
            const int idx = tid + it * 128;
            const int row = idx >> 3, q = idx & 7;
            const uint32_t sw = (uint32_t)(q * 16) ^ ((uint32_t)(row & 7) << 4);
            cpa16(sb + OFF_K + row * 128 + sw, srcK + (size_t)row * CH + q * 8);
            cpa16(sb + OFF_V + row * 128 + sw, srcV + (size_t)row * LP + q * 8);
        }
        cpa_commit();
    }

    // ---- Q tile: load, scale (0.125 * log2e folded), fp16, swizzled [t][c] ----
    for (int i = tid; i < BT * CH; i += NTH) {
        const int t = i & 127, c = i >> 7;
        const float v = qb[(size_t)c * T + t0 + t] * (0.125f * LOG2E);
        const uint32_t off = (uint32_t)(t * 128 + c * 2) ^ ((uint32_t)(t & 7) << 4);
        *(__half*)(smc + OFF_Q + off) = __float2half(v);
    }

    // ---- ldmatrix lane address geometry (SW128) ----
    const int mi = lane >> 3, ri = lane & 7;
    const uint32_t a_row  = (mi & 1) * 8 + ri;        // A m16k16
    const uint32_t a_koff = (mi >> 1) * 16;
    const uint32_t b_row  = (mi >> 1) * 8 + ri;       // B n16k16
    const uint32_t b_koff = (mi & 1) * 16;
    const uint32_t a_sw = (a_row & 7) << 4;
    const uint32_t b_sw = (b_row & 7) << 4;

    // warp covers rows [warp*32, warp*32+32): two m16 A tiles
    const uint32_t q_base0 = sb + OFF_Q + (warp * 32 + a_row) * 128;
    const uint32_t q_base1 = q_base0 + 16 * 128;
    const uint32_t kB = sb + OFF_K + b_row * 128;
    const uint32_t vB = sb + OFF_V + b_row * 128;

    const int trow0 = t0 + warp * 32 + (lane >> 2);   // +8, +16, +24 siblings

    float oaccA[8][4] = {}, oaccB[8][4] = {};
    float ls0 = 0.f, ls1 = 0.f, ls2 = 0.f, ls3 = 0.f;

    for (int tile = 0; tile < NTILES; tile++) {
        const int s0 = tile * BS;
        const uint32_t buf = (uint32_t)(tile & 1) * KVBUF;

        cpa_wait_all();
        __syncthreads();

        // ---- prefetch tile+1 into other buffer (overlaps with compute) ----
        if (tile + 1 < NTILES) {
            const uint32_t nbuf = (uint32_t)((tile + 1) & 1) * KVBUF;
            const int ns0 = s0 + BS;
            #pragma unroll
            for (int it = 0; it < 4; it++) {
                const int idx = tid + it * 128;
                const int row = idx >> 3, q = idx & 7;
                const uint32_t sw = (uint32_t)(q * 16) ^ ((uint32_t)(row & 7) << 4);
                cpa16(sb + OFF_K + nbuf + row * 128 + sw,
                      srcK + (size_t)(ns0 + row) * CH + q * 8);
                cpa16(sb + OFF_V + nbuf + row * 128 + sw,
                      srcV + (size_t)row * LP + ns0 + q * 8);
            }
            cpa_commit();
        }

        const bool hot = (!mflag && tile < NTILES - 1);

        // ---- fused per-s-block loop: GEMM1(blk) -> softmax(blk) -> GEMM2(blk)
        //      independent blocks let HMMA overlap MUFU; only 16 score regs live
        #pragma unroll
        for (int sblk = 0; sblk < 4; sblk++) {
            float sA0[4] = {}, sA1[4] = {}, sB0[4] = {}, sB1[4] = {};
            #pragma unroll
            for (int kk = 0; kk < 4; kk++) {
                uint32_t a0[4], a1[4], bk[4];
                ldsm4(a0, q_base0 + ((a_koff + kk * 32) ^ a_sw));
                ldsm4(a1, q_base1 + ((a_koff + kk * 32) ^ a_sw));
                ldsm4(bk, kB + buf + sblk * 2048 + ((b_koff + kk * 32) ^ b_sw));
                mma_f16(sA0, a0, bk[0], bk[1]);
                mma_f16(sA1, a0, bk[2], bk[3]);
                mma_f16(sB0, a1, bk[0], bk[1]);
                mma_f16(sB1, a1, bk[2], bk[3]);
            }

            // softmax on this 16-key block
            if (hot) {
                #pragma unroll
                for (int e = 0; e < 4; e++) {
                    sA0[e] = ex2(sA0[e]); sA1[e] = ex2(sA1[e]);
                    sB0[e] = ex2(sB0[e]); sB1[e] = ex2(sB1[e]);
                }
                ls0 += sA0[0] + sA0[1] + sA1[0] + sA1[1];
                ls1 += sA0[2] + sA0[3] + sA1[2] + sA1[3];
                ls2 += sB0[0] + sB0[1] + sB1[0] + sB1[1];
                ls3 += sB0[2] + sB0[3] + sB1[2] + sB1[3];
            } else {
                const int sgb = s0 + sblk * 16 + 2 * (lane & 3);
                #pragma unroll
                for (int h = 0; h < 2; h++) {          // h=0: sX0 (k0-7), h=1: sX1 (k8-15)
                    float* pA = h ? sA1 : sA0;
                    float* pB = h ? sB1 : sB0;
                    #pragma unroll
                    for (int e = 0; e < 4; e++) {
                        const int sg = sgb + h * 8 + (e & 1);
                        float scA = pA[e], scB = pB[e];
                        if (mflag && sg < L) {
                            const int ra = trow0 + ((e < 2) ? 0 : 8);
                            scA += mask[(size_t)ra * L + sg] * LOG2E;
                            scB += mask[(size_t)(ra + 16) * L + sg] * LOG2E;
                        }
                        float pAv = ex2(scA), pBv = ex2(scB);
                        pAv = (sg < L) ? pAv : 0.f;
                        pBv = (sg < L) ? pBv : 0.f;
                        pA[e] = pAv;
                        pB[e] = pBv;
                        if (e < 2) { ls0 += pAv; ls2 += pBv; }
                        else       { ls1 += pAv; ls3 += pBv; }
                    }
                }
            }

            // pack P block -> fp16 A-frags (k16 = this s-block)
            uint32_t aA[4], aB[4];
            aA[0] = f2h2(sA0[0], sA0[1]);
            aA[1] = f2h2(sA0[2], sA0[3]);
            aA[2] = f2h2(sA1[0], sA1[1]);
            aA[3] = f2h2(sA1[2], sA1[3]);
            aB[0] = f2h2(sB0[0], sB0[1]);
            aB[1] = f2h2(sB0[2], sB0[3]);
            aB[2] = f2h2(sB1[0], sB1[1]);
            aB[3] = f2h2(sB1[2], sB1[3]);

            // GEMM2 partial: O += P(blk) * V(blk, :)
            #pragma unroll
            for (int nb2 = 0; nb2 < 4; nb2++) {
                uint32_t bv[4];
                ldsm4(bv, vB + buf + nb2 * 2048 + ((b_koff + sblk * 32) ^ b_sw));
                mma_f16(oaccA[2 * nb2],     aA, bv[0], bv[1]);
                mma_f16(oaccA[2 * nb2 + 1], aA, bv[2], bv[3]);
                mma_f16(oaccB[2 * nb2],     aB, bv[0], bv[1]);
                mma_f16(oaccB[2 * nb2 + 1], aB, bv[2], bv[3]);
            }
        }
    }

    // ---- epilogue: reduce row sums, normalize, stage transpose, store ----
    ls0 += __shfl_xor_sync(0xffffffffu, ls0, 1);
    ls0 += __shfl_xor_sync(0xffffffffu, ls0, 2);
    ls1 += __shfl_xor_sync(0xffffffffu, ls1, 1);
    ls1 += __shfl_xor_sync(0xffffffffu, ls1, 2);
    ls2 += __shfl_xor_sync(0xffffffffu, ls2, 1);
    ls2 += __shfl_xor_sync(0xffffffffu, ls2, 2);
    ls3 += __shfl_xor_sync(0xffffffffu, ls3, 1);
    ls3 += __shfl_xor_sync(0xffffffffu, ls3, 2);
    const float rl0 = 1.0f / ls0, rl1 = 1.0f / ls1;
    const float rl2 = 1.0f / ls2, rl3 = 1.0f / ls3;

    __syncthreads();                           // done with Q/K/V smem
    float* os = (float*)smc;                   // reuse: [CH][132]
    const int tl0 = warp * 32 + (lane >> 2);
    #pragma unroll
    for (int jb = 0; jb < 8; jb++) {
        const int c0 = jb * 8 + 2 * (lane & 3);
        os[c0 * 132 + tl0]              = oaccA[jb][0] * rl0;
        os[(c0 + 1) * 132 + tl0]        = oaccA[jb][1] * rl0;
        os[c0 * 132 + tl0 + 8]          = oaccA[jb][2] * rl1;
        os[(c0 + 1) * 132 + tl0 + 8]    = oaccA[jb][3] * rl1;
        os[c0 * 132 + tl0 + 16]         = oaccB[jb][0] * rl2;
        os[(c0 + 1) * 132 + tl0 + 16]   = oaccB[jb][1] * rl2;
        os[c0 * 132 + tl0 + 24]         = oaccB[jb][2] * rl3;
        os[(c0 + 1) * 132 + tl0 + 24]   = oaccB[jb][3] * rl3;
    }
    __syncthreads();

    float* ob = out + (size_t)b * CH * T + t0;
    for (int i = tid; i < CH * BT; i += NTH) {
        const int c = i >> 7, t = i & 127;
        ob[(size_t)c * T + t] = os[c * 132 + t];
    }
}

} // anonymous namespace

extern "C" void kernel_launch(void* const* d_in, const int* in_sizes, int n_in,
                              void* d_out, int out_size)
{
    const float* qkv  = (const float*)d_in[0];
    const float* ekv  = (const float*)d_in[1];
    const float* mask = (const float*)d_in[2];
    float* out = (float*)d_out;
    (void)n_in; (void)out_size;

    cudaFuncSetAttribute(attn_kernel,
                         cudaFuncAttributeMaxDynamicSharedMemorySize, SMEM_TOTAL);

    reset_flag_kernel<<<1, 1>>>();
    scan_mask_kernel<<<1024, 256>>>(mask, in_sizes[2]);
    prepass_kernel<<<dim3(LP / 64, NB), 256>>>(qkv, ekv);

    dim3 grid(T / BT, NB);   // 16 x 32 = 512 CTAs -> single wave at 4 CTAs/SM
    attn_kernel<<<grid, NTH, SMEM_TOTAL>>>(qkv, mask, out);
}